// round 15
// baseline (speedup 1.0000x reference)
#include <cuda_runtime.h>
#include <cuda_fp16.h>
#include <math.h>
#include <stdint.h>

#define D_BB 768
#define CH   64           // k per sub-chunk
#define NCH  15           // sub-chunks
#define NPAIR 8           // chunk pairs (last pair = chunk 14 only)
#define SUBB 20480        // per sub-stage: A 4K | B 16K
#define SMEM_TOTAL (6 * SUBB)   // 3 pair-stages x 2 sub-stages = 122880

typedef unsigned long long u64;
typedef unsigned int       u32;

// ---- helpers -----------------------------------------------------------------
__device__ __forceinline__ u32 smem_u32(const void* p) {
    u32 a;
    asm("{ .reg .u64 t; cvta.to.shared.u64 t, %1; cvt.u32.u64 %0, t; }"
        : "=r"(a) : "l"(p));
    return a;
}
__device__ __forceinline__ u32 SWZ(u32 b)  { return b ^ ((b >> 3) & 0x70); }  // 128B rows (A)
__device__ __forceinline__ u32 SWZB(u32 b) { return b ^ ((b >> 4) & 0x70); }  // 256B rows (B)

__device__ __forceinline__ u32 pack_h2(float lo, float hi) {
    __half2 v = __floats2half2_rn(lo, hi);
    return *(u32*)&v;
}

#define LDMX4(r, addr) \
    asm volatile("ldmatrix.sync.aligned.m8n8.x4.shared.b16 {%0,%1,%2,%3}, [%4];" \
        : "=r"((r)[0]), "=r"((r)[1]), "=r"((r)[2]), "=r"((r)[3]) : "r"(addr))

#define LDMX4T(r, addr) \
    asm volatile("ldmatrix.sync.aligned.m8n8.x4.trans.shared.b16 {%0,%1,%2,%3}, [%4];" \
        : "=r"((r)[0]), "=r"((r)[1]), "=r"((r)[2]), "=r"((r)[3]) : "r"(addr))

#define MMAF16(d, a, b0, b1) \
    asm volatile("mma.sync.aligned.m16n8k16.row.col.f32.f16.f16.f32 " \
        "{%0,%1,%2,%3}, {%4,%5,%6,%7}, {%8,%9}, {%0,%1,%2,%3};" \
        : "+f"((d)[0]), "+f"((d)[1]), "+f"((d)[2]), "+f"((d)[3]) \
        : "r"((a)[0]), "r"((a)[1]), "r"((a)[2]), "r"((a)[3]), "r"(b0), "r"(b1))

#define STS64(r0, r1, sa) \
    asm volatile("st.shared.v2.b32 [%0], {%1, %2};" \
        :: "r"(sa), "r"(r0), "r"(r1) : "memory")

// -----------------------------------------------------------------------------
// Single fused kernel: grid = T/32 CTAs, 512 threads.
// 16 warps = 2M x 2N x 4K-groups; warp tile 16 rows x 64 cols.
// Paired-chunk pipeline: 3 pair-stages, ONE sync per 2 chunks.
// B stored k-major in smem ([k][128n], 256B rows), fragments via ldmatrix.trans.
// -----------------------------------------------------------------------------
__global__ void __launch_bounds__(512)
critic_mma(const float* __restrict__ bb,
           const float* __restrict__ res,   const float* __restrict__ fr,
           const float* __restrict__ estep, const float* __restrict__ enode,
           const float* __restrict__ ccl,   const float* __restrict__ cnd,
           const float* __restrict__ W1,    const float* __restrict__ b1,
           const float* __restrict__ W3, const float* __restrict__ b3,
           const float* __restrict__ W4, const float* __restrict__ b4,
           const float* __restrict__ W5, const float* __restrict__ b5,
           const float* __restrict__ W6, const float* __restrict__ b6,
           float* __restrict__ out, int T)
{
    extern __shared__ __align__(16) char dsm[];
    const u32 sb = smem_u32(dsm);

    const int tid  = threadIdx.x;
    const int lane = tid & 31;
    const int wid  = tid >> 5;
    const int mbase = blockIdx.x * 32;

    const int kg = wid & 3;
    const int mg = (wid >> 2) & 1;
    const int ng = wid >> 3;

    // sub-stage base for chunk c: pair (c>>1)%3, half c&1
    auto stageBase = [&](int c) -> u32 {
        return sb + (u32)((((c >> 1) % 3) * 2 + (c & 1)) * SUBB);
    };

    // ---- A loader mapping: thread -> (row, 4 consecutive k) ----
    const int ar = tid >> 4;
    const int ak = (tid & 15) * 4;
    int atask = mbase + ar; if (atask >= T) atask = T - 1;
    const float* bbrow = bb + (size_t)atask * D_BB;
    const u32 aoff = SWZ((u32)(ar * 128 + ak * 2));

    // ---- B loader mapping: 4 x (k row, 4 consecutive n) per thread ----
    int bkl[4], bn4[4]; u32 bsts[4];
    #pragma unroll
    for (int i = 0; i < 4; i++) {
        int id = tid + i * 512;              // 2048 = 64 k x 32 n-groups
        bkl[i] = id >> 5;                    // k within chunk (warp-uniform)
        bn4[i] = (id & 31) * 4;              // n start
        bsts[i] = SWZB((u32)(bkl[i] * 256 + bn4[i] * 2));
    }

    // ---- fragment offsets ----
    const u32 aOff = SWZ((u32)((mg * 16 + (lane & 7) + ((lane >> 3) & 1) * 8) * 128
                               + (lane >> 4) * 16 + kg * 32));
    // B trans fragments: matrices (k0-7,n0-7),(k8-15,n0-7),(k0-7,n8-15),(k8-15,n8-15)
    u32 bOff[4];
    #pragma unroll
    for (int j = 0; j < 4; j++) {
        int krow = kg * 16 + ((lane >> 3) & 1) * 8 + (lane & 7);
        int ncol = ng * 64 + j * 16 + (lane >> 4) * 8;
        bOff[j] = SWZB((u32)(krow * 256 + ncol * 2));
    }

    float Da[8][4];
    #pragma unroll
    for (int j = 0; j < 8; j++)
        #pragma unroll
        for (int q = 0; q < 4; q++) Da[j][q] = 0.f;

    auto loadA_gen = [&](int c, float* x) {
        int g0 = c * CH + ak;
        if (g0 >= 160 && g0 + 4 <= 928) {
            float4 v = *(const float4*)(bbrow + (g0 - 160));
            x[0] = v.x; x[1] = v.y; x[2] = v.z; x[3] = v.w;
        } else {
            #pragma unroll
            for (int j = 0; j < 4; j++) {
                int gk = g0 + j;
                float v = 0.f;
                if (gk < 150) {
                    int nn = gk / 30, rem = gk - nn * 30;
                    int mm = rem / 6, oo = rem - mm * 6;
                    v = res[atask * 5 + nn] * fr[atask * 5 + mm] * estep[atask * 6 + oo];
                } else if (gk >= 160 && gk < 928) {
                    v = bbrow[gk - 160];
                }
                x[j] = v;
            }
        }
    };
    auto loadA_bb = [&](int c, float* x) {
        int g0 = c * CH + ak;
        if (g0 + 4 <= 928) {
            float4 v = *(const float4*)(bbrow + (g0 - 160));
            x[0] = v.x; x[1] = v.y; x[2] = v.z; x[3] = v.w;
        } else {
            x[0] = x[1] = x[2] = x[3] = 0.f;
        }
    };
    auto storeA = [&](int c, const float* x) {
        const u32 base = stageBase(c);
        STS64(pack_h2(x[0], x[1]), pack_h2(x[2], x[3]), base + aoff);
    };

    // B: 4 x float4 from W1 rows (remap 918->960, warp-uniform guards)
    auto loadB = [&](int c, float4* y) {
        #pragma unroll
        for (int i = 0; i < 4; i++) {
            int gk = c * CH + bkl[i];
            int sr = (gk < 160) ? gk : gk - 10;
            if (gk < 150 || (gk >= 160 && gk < 928))
                y[i] = *(const float4*)(W1 + (size_t)sr * 128 + bn4[i]);
            else
                y[i] = make_float4(0.f, 0.f, 0.f, 0.f);
        }
    };
    auto storeB = [&](int c, const float4* y) {
        const u32 base = stageBase(c) + 4096;
        #pragma unroll
        for (int i = 0; i < 4; i++)
            STS64(pack_h2(y[i].x, y[i].y), pack_h2(y[i].z, y[i].w),
                  base + bsts[i]);
    };

    auto compute = [&](int c) {
        const u32 base = stageBase(c);
        u32 ah[4], bf[4][4];
        LDMX4(ah, base + aOff);
        #pragma unroll
        for (int j = 0; j < 4; j++) LDMX4T(bf[j], base + 4096 + bOff[j]);
        #pragma unroll
        for (int j = 0; j < 4; j++) {
            MMAF16(Da[2*j],   ah, bf[j][0], bf[j][1]);
            MMAF16(Da[2*j+1], ah, bf[j][2], bf[j][3]);
        }
    };

    // ---- prologue: pairs 0,1 staged; pair 2 prefetched to regs ----
    float xa[4], xb[4];
    float4 ya[4], yb[4];
    loadA_gen(0, xa); loadB(0, ya);
    loadA_gen(1, xb); loadB(1, yb);
    storeA(0, xa); storeB(0, ya);
    storeA(1, xb); storeB(1, yb);
    loadA_gen(2, xa); loadB(2, ya);
    loadA_gen(3, xb); loadB(3, yb);
    storeA(2, xa); storeB(2, ya);
    storeA(3, xb); storeB(3, yb);
    loadA_bb(4, xa); loadB(4, ya);
    loadA_bb(5, xb); loadB(5, yb);
    __syncthreads();

    // ---- main loop: one sync per pair ----
    for (int p = 0; p < NPAIR; p++) {
        const int c0 = 2 * p;
        compute(c0);
        if (c0 + 1 < NCH) compute(c0 + 1);

        if (p + 2 < NPAIR) {
            const int cA = c0 + 4, cB = c0 + 5;
            storeA(cA, xa); storeB(cA, ya);
            if (cB < NCH) { storeA(cB, xb); storeB(cB, yb); }
            if (p + 3 < NPAIR) {
                loadA_bb(cA + 2, xa); loadB(cA + 2, ya);
                if (cB + 2 < NCH) { loadA_bb(cB + 2, xb); loadB(cB + 2, yb); }
            }
        }
        __syncthreads();
    }

    // ---- write kg-partial D to smem: hsm[4][32][132] ----
    float* hsm = (float*)dsm;
    {
        float* slab = hsm + kg * (32 * 132);
        const int r0 = mg * 16 + (lane >> 2);
        #pragma unroll
        for (int j = 0; j < 4; j++) {
            #pragma unroll
            for (int h2 = 0; h2 < 2; h2++) {
                int jj = 2 * j + h2;
                int col = ng * 64 + j * 16 + h2 * 8 + 2 * (lane & 3);
                *(float2*)&slab[r0 * 132 + col]       = make_float2(Da[jj][0], Da[jj][1]);
                *(float2*)&slab[(r0 + 8) * 132 + col] = make_float2(Da[jj][2], Da[jj][3]);
            }
        }
    }
    __syncthreads();

    // ---- epilogue: 16 warps x 2 tasks; reduce 4 kg slabs inline ----
    const int n0 = lane * 4;
    const float4 bj = *(const float4*)&b1[n0];
    const float4 w3 = *(const float4*)&W3[n0];
    const float4 w4 = *(const float4*)&W4[n0];
    const float4 w5 = *(const float4*)&W5[n0];
    const float4 w6 = *(const float4*)&W6[n0];
    const float B3 = b3[0], B4 = b4[0], B5 = b5[0], B6 = b6[0];

    #pragma unroll
    for (int it = 0; it < 2; it++) {
        int m = wid * 2 + it;
        int task = mbase + m;
        bool ok = (task < T);
        int rt = ok ? task : (T - 1);

        float4 s = *(const float4*)&hsm[m * 132 + n0];
        #pragma unroll
        for (int q = 1; q < 4; q++) {
            float4 p2 = *(const float4*)&hsm[q * (32 * 132) + m * 132 + n0];
            s.x += p2.x; s.y += p2.y; s.z += p2.z; s.w += p2.w;
        }
        float h0 = fmaxf(s.x + bj.x, 0.f), h1 = fmaxf(s.y + bj.y, 0.f);
        float h2 = fmaxf(s.z + bj.z, 0.f), h3 = fmaxf(s.w + bj.w, 0.f);
        float p3 = h0*w3.x + h1*w3.y + h2*w3.z + h3*w3.w;
        float p4 = h0*w4.x + h1*w4.y + h2*w4.z + h3*w4.w;
        float p5 = h0*w5.x + h1*w5.y + h2*w5.z + h3*w5.w;
        float p6 = h0*w6.x + h1*w6.y + h2*w6.z + h3*w6.w;

        float se = enode[(size_t)rt * 64 + lane] + enode[(size_t)rt * 64 + lane + 32];
        float sc = (lane < 4) ? ccl[rt * 4 + lane] : 0.0f;
        float sn = cnd[(size_t)rt * 32 + lane];

        #pragma unroll
        for (int off = 16; off; off >>= 1) {
            p3 += __shfl_xor_sync(0xffffffffu, p3, off);
            p4 += __shfl_xor_sync(0xffffffffu, p4, off);
            p5 += __shfl_xor_sync(0xffffffffu, p5, off);
            p6 += __shfl_xor_sync(0xffffffffu, p6, off);
            se += __shfl_xor_sync(0xffffffffu, se, off);
            sc += __shfl_xor_sync(0xffffffffu, sc, off);
            sn += __shfl_xor_sync(0xffffffffu, sn, off);
        }
        if (lane == 0 && ok) {
            float me = se * (1.0f / 64.0f);
            float ss = sc * sn;
            float y51 = 1.0f / (1.0f + expf(-(p3 * me + B3)));
            float y61 = p4 * me + B4;
            float y52 = 1.0f / (1.0f + expf(-(p5 * ss + B5)));
            float y62 = p6 * ss + B6;
            float p2 = y51 * y52;
            out[task] = (1.0f - p2) * (-100.0f) + p2 * (y61 + y62);
        }
    }
}

// -----------------------------------------------------------------------------
extern "C" void kernel_launch(void* const* d_in, const int* in_sizes, int n_in,
                              void* d_out, int out_size) {
    const float* bb    = (const float*)d_in[2];
    const float* res   = (const float*)d_in[3];
    const float* fr    = (const float*)d_in[4];
    const float* estep = (const float*)d_in[5];
    const float* enode = (const float*)d_in[6];
    const float* ccl   = (const float*)d_in[7];
    const float* cnd   = (const float*)d_in[8];
    const float* W1    = (const float*)d_in[9];
    const float* b1    = (const float*)d_in[10];
    const float* W3    = (const float*)d_in[11];
    const float* b3    = (const float*)d_in[12];
    const float* W4    = (const float*)d_in[13];
    const float* b4    = (const float*)d_in[14];
    const float* W5    = (const float*)d_in[15];
    const float* b5    = (const float*)d_in[16];
    const float* W6    = (const float*)d_in[17];
    const float* b6    = (const float*)d_in[18];

    int T = in_sizes[2] / D_BB;

    static int cfg = 0;
    if (!cfg) {
        cudaFuncSetAttribute(critic_mma,
                             cudaFuncAttributeMaxDynamicSharedMemorySize,
                             SMEM_TOTAL);
        cfg = 1;
    }

    critic_mma<<<(T + 31) / 32, 512, SMEM_TOTAL>>>(
        bb, res, fr, estep, enode, ccl, cnd, W1,
        b1, W3, b3, W4, b4, W5, b5, W6, b6, (float*)d_out, T);
}

// round 16
// speedup vs baseline: 1.1552x; 1.1552x over previous
#include <cuda_runtime.h>
#include <cuda_fp16.h>
#include <math.h>
#include <stdint.h>

#define D_BB 768
#define KPAD 960          // 160 feat(+pad) + 768 bb + 32 pad
#define CH   64           // k per sub-chunk
#define NCH  15           // sub-chunks
#define NPAIR 8           // chunk pairs (last pair = chunk 14 only)
#define SUBB 20480        // per sub-stage: A 4K | B 16K
#define SMEM_TOTAL (6 * SUBB)   // 3 pair-stages x 2 sub-stages = 122880

typedef unsigned long long u64;
typedef unsigned int       u32;

// ---- W1 pre-converted fp16, SAME orientation as W1 ([k][n]), remapped/padded --
__device__ __align__(16) __half g_Bkm[KPAD * 128];
__device__ u32 g_sync;      // monotonic epoch counter (replay-safe)

// ---- helpers -----------------------------------------------------------------
__device__ __forceinline__ u32 smem_u32(const void* p) {
    u32 a;
    asm("{ .reg .u64 t; cvta.to.shared.u64 t, %1; cvt.u32.u64 %0, t; }"
        : "=r"(a) : "l"(p));
    return a;
}
__device__ __forceinline__ u32 SWZ(u32 b)  { return b ^ ((b >> 3) & 0x70); }  // 128B rows (A)
__device__ __forceinline__ u32 SWZB(u32 b) { return b ^ ((b >> 4) & 0x70); }  // 256B rows (B)

__device__ __forceinline__ u32 pack_h2(float lo, float hi) {
    __half2 v = __floats2half2_rn(lo, hi);
    return *(u32*)&v;
}

#define LDMX4(r, addr) \
    asm volatile("ldmatrix.sync.aligned.m8n8.x4.shared.b16 {%0,%1,%2,%3}, [%4];" \
        : "=r"((r)[0]), "=r"((r)[1]), "=r"((r)[2]), "=r"((r)[3]) : "r"(addr))

#define LDMX4T(r, addr) \
    asm volatile("ldmatrix.sync.aligned.m8n8.x4.trans.shared.b16 {%0,%1,%2,%3}, [%4];" \
        : "=r"((r)[0]), "=r"((r)[1]), "=r"((r)[2]), "=r"((r)[3]) : "r"(addr))

#define MMAF16(d, a, b0, b1) \
    asm volatile("mma.sync.aligned.m16n8k16.row.col.f32.f16.f16.f32 " \
        "{%0,%1,%2,%3}, {%4,%5,%6,%7}, {%8,%9}, {%0,%1,%2,%3};" \
        : "+f"((d)[0]), "+f"((d)[1]), "+f"((d)[2]), "+f"((d)[3]) \
        : "r"((a)[0]), "r"((a)[1]), "r"((a)[2]), "r"((a)[3]), "r"(b0), "r"(b1))

#define CPA16(dst, src) \
    asm volatile("cp.async.cg.shared.global [%0], [%1], 16;" \
        :: "r"(dst), "l"(src) : "memory")
#define CPA_COMMIT() asm volatile("cp.async.commit_group;" ::: "memory")
#define CPA_WAIT(n)  asm volatile("cp.async.wait_group %0;" :: "n"(n) : "memory")

#define STS64(r0, r1, sa) \
    asm volatile("st.shared.v2.b32 [%0], {%1, %2};" \
        :: "r"(sa), "r"(r0), "r"(r1) : "memory")

// -----------------------------------------------------------------------------
// Single fused kernel: grid = T/32 CTAs, 512 threads.
// Phase 0: cooperative W1 fp32->fp16 conversion (coalesced, same layout) +
//          grid-wide epoch-counter barrier (all CTAs co-resident: grid <= #SM).
// Phase 1: 16 warps = 2M x 2N x 4K-groups; warp tile 16 rows x 64 cols.
//          Paired-chunk pipeline (3 pair-stages, 1 sync / 2 chunks),
//          B via cp.async of fp16, fragments via ldmatrix.trans.
// -----------------------------------------------------------------------------
__global__ void __launch_bounds__(512)
critic_mma(const float* __restrict__ bb,
           const float* __restrict__ res,   const float* __restrict__ fr,
           const float* __restrict__ estep, const float* __restrict__ enode,
           const float* __restrict__ ccl,   const float* __restrict__ cnd,
           const float* __restrict__ W1,    const float* __restrict__ b1,
           const float* __restrict__ W3, const float* __restrict__ b3,
           const float* __restrict__ W4, const float* __restrict__ b4,
           const float* __restrict__ W5, const float* __restrict__ b5,
           const float* __restrict__ W6, const float* __restrict__ b6,
           float* __restrict__ out, int T)
{
    extern __shared__ __align__(16) char dsm[];
    const u32 sb = smem_u32(dsm);

    const int tid  = threadIdx.x;
    const int lane = tid & 31;
    const int wid  = tid >> 5;
    const int mbase = blockIdx.x * 32;

    // ---- Phase 0: convert W1 -> g_Bkm (fp16, [k][n], remap+pad) ----
    {
        int id = blockIdx.x * 512 + tid;          // up to 65536 workers
        if (id < KPAD * 32) {                     // 30720 items of 4 values
            int k  = id >> 5;
            int n4 = (id & 31) * 4;
            int sr = (k < 160) ? k : k - 10;
            float4 v = make_float4(0.f, 0.f, 0.f, 0.f);
            if (k < 150 || (k >= 160 && k < 928))
                v = *(const float4*)(W1 + (size_t)sr * 128 + n4);
            *(u64*)&g_Bkm[(size_t)k * 128 + n4] =
                (u64)pack_h2(v.x, v.y) | ((u64)pack_h2(v.z, v.w) << 32);
        }
        __threadfence();
        if (tid == 0) {
            u32 old = atomicAdd(&g_sync, 1u);
            u32 target = (old / gridDim.x) * gridDim.x + gridDim.x;
            while (atomicAdd(&g_sync, 0u) < target) { }
            __threadfence();
        }
        __syncthreads();
    }

    const int kg = wid & 3;
    const int mg = (wid >> 2) & 1;
    const int ng = wid >> 3;

    // sub-stage base for chunk c: pair (c>>1)%3, half c&1
    auto stageBase = [&](int c) -> u32 {
        return sb + (u32)((((c >> 1) % 3) * 2 + (c & 1)) * SUBB);
    };

    // ---- A loader mapping: thread -> (row, 4 consecutive k) ----
    const int ar = tid >> 4;
    const int ak = (tid & 15) * 4;
    int atask = mbase + ar; if (atask >= T) atask = T - 1;
    const float* bbrow = bb + (size_t)atask * D_BB;
    const u32 aoff = SWZ((u32)(ar * 128 + ak * 2));

    // ---- B cp.async mapping: 2 x (k row, 16B seg) per thread ----
    int bkr[2], bsg[2]; u32 bdst[2];
    #pragma unroll
    for (int i = 0; i < 2; i++) {
        int id = tid + i * 512;              // 1024 = 64 k-rows x 16 segs
        bkr[i] = id >> 4;
        bsg[i] = id & 15;
        bdst[i] = SWZB((u32)(bkr[i] * 256 + bsg[i] * 16));
    }

    // ---- fragment offsets ----
    const u32 aOff = SWZ((u32)((mg * 16 + (lane & 7) + ((lane >> 3) & 1) * 8) * 128
                               + (lane >> 4) * 16 + kg * 32));
    u32 bOff[4];
    #pragma unroll
    for (int j = 0; j < 4; j++) {
        int krow = kg * 16 + ((lane >> 3) & 1) * 8 + (lane & 7);
        int ncol = ng * 64 + j * 16 + (lane >> 4) * 8;
        bOff[j] = SWZB((u32)(krow * 256 + ncol * 2));
    }

    float Da[8][4];
    #pragma unroll
    for (int j = 0; j < 8; j++)
        #pragma unroll
        for (int q = 0; q < 4; q++) Da[j][q] = 0.f;

    auto loadA_gen = [&](int c, float* x) {
        int g0 = c * CH + ak;
        if (g0 >= 160 && g0 + 4 <= 928) {
            float4 v = *(const float4*)(bbrow + (g0 - 160));
            x[0] = v.x; x[1] = v.y; x[2] = v.z; x[3] = v.w;
        } else {
            #pragma unroll
            for (int j = 0; j < 4; j++) {
                int gk = g0 + j;
                float v = 0.f;
                if (gk < 150) {
                    int nn = gk / 30, rem = gk - nn * 30;
                    int mm = rem / 6, oo = rem - mm * 6;
                    v = res[atask * 5 + nn] * fr[atask * 5 + mm] * estep[atask * 6 + oo];
                } else if (gk >= 160 && gk < 928) {
                    v = bbrow[gk - 160];
                }
                x[j] = v;
            }
        }
    };
    auto loadA_bb = [&](int c, float* x) {
        int g0 = c * CH + ak;
        if (g0 + 4 <= 928) {
            float4 v = *(const float4*)(bbrow + (g0 - 160));
            x[0] = v.x; x[1] = v.y; x[2] = v.z; x[3] = v.w;
        } else {
            x[0] = x[1] = x[2] = x[3] = 0.f;
        }
    };
    auto storeA = [&](int c, const float* x) {
        const u32 base = stageBase(c);
        STS64(pack_h2(x[0], x[1]), pack_h2(x[2], x[3]), base + aoff);
    };
    auto issueB = [&](int c) {
        const u32 base = stageBase(c) + 4096;
        #pragma unroll
        for (int i = 0; i < 2; i++) {
            const __half* src = g_Bkm + (size_t)(c * CH + bkr[i]) * 128 + bsg[i] * 8;
            CPA16(base + bdst[i], src);
        }
    };
    auto compute = [&](int c) {
        const u32 base = stageBase(c);
        u32 ah[4], bf[4][4];
        LDMX4(ah, base + aOff);
        #pragma unroll
        for (int j = 0; j < 4; j++) LDMX4T(bf[j], base + 4096 + bOff[j]);
        #pragma unroll
        for (int j = 0; j < 4; j++) {
            MMAF16(Da[2*j],   ah, bf[j][0], bf[j][1]);
            MMAF16(Da[2*j+1], ah, bf[j][2], bf[j][3]);
        }
    };

    // ---- prologue: pairs 0,1 staged; A for pair 2 prefetched ----
    float xa[4], xb[4];
    loadA_gen(0, xa); loadA_gen(1, xb);
    storeA(0, xa); storeA(1, xb); issueB(0); issueB(1); CPA_COMMIT();
    loadA_gen(2, xa); loadA_gen(3, xb);
    storeA(2, xa); storeA(3, xb); issueB(2); issueB(3); CPA_COMMIT();
    loadA_bb(4, xa); loadA_bb(5, xb);
    CPA_WAIT(1);             // pair 0 arrived
    __syncthreads();

    // ---- main loop: one sync per pair ----
    for (int p = 0; p < NPAIR; p++) {
        const int c0 = 2 * p;
        compute(c0);
        if (c0 + 1 < NCH) compute(c0 + 1);

        if (p + 2 < NPAIR) {
            const int cA = c0 + 4, cB = c0 + 5;
            storeA(cA, xa);
            if (cB < NCH) storeA(cB, xb);
            if (p + 3 < NPAIR) {
                loadA_bb(cA + 2, xa);
                if (cB + 2 < NCH) loadA_bb(cB + 2, xb);
            }
            issueB(cA);
            if (cB < NCH) issueB(cB);
            CPA_COMMIT();
            CPA_WAIT(1);     // pair p+1 arrived
        } else if (p + 1 < NPAIR) {
            CPA_WAIT(0);     // final pair arrived
        }
        __syncthreads();
    }

    // ---- write kg-partial D to smem: hsm[4][32][132] ----
    float* hsm = (float*)dsm;
    {
        float* slab = hsm + kg * (32 * 132);
        const int r0 = mg * 16 + (lane >> 2);
        #pragma unroll
        for (int j = 0; j < 4; j++) {
            #pragma unroll
            for (int h2 = 0; h2 < 2; h2++) {
                int jj = 2 * j + h2;
                int col = ng * 64 + j * 16 + h2 * 8 + 2 * (lane & 3);
                *(float2*)&slab[r0 * 132 + col]       = make_float2(Da[jj][0], Da[jj][1]);
                *(float2*)&slab[(r0 + 8) * 132 + col] = make_float2(Da[jj][2], Da[jj][3]);
            }
        }
    }
    __syncthreads();

    // ---- epilogue: 16 warps x 2 tasks; reduce 4 kg slabs inline ----
    const int n0 = lane * 4;
    const float4 bj = *(const float4*)&b1[n0];
    const float4 w3 = *(const float4*)&W3[n0];
    const float4 w4 = *(const float4*)&W4[n0];
    const float4 w5 = *(const float4*)&W5[n0];
    const float4 w6 = *(const float4*)&W6[n0];
    const float B3 = b3[0], B4 = b4[0], B5 = b5[0], B6 = b6[0];

    #pragma unroll
    for (int it = 0; it < 2; it++) {
        int m = wid * 2 + it;
        int task = mbase + m;
        bool ok = (task < T);
        int rt = ok ? task : (T - 1);

        float4 s = *(const float4*)&hsm[m * 132 + n0];
        #pragma unroll
        for (int q = 1; q < 4; q++) {
            float4 p2 = *(const float4*)&hsm[q * (32 * 132) + m * 132 + n0];
            s.x += p2.x; s.y += p2.y; s.z += p2.z; s.w += p2.w;
        }
        float h0 = fmaxf(s.x + bj.x, 0.f), h1 = fmaxf(s.y + bj.y, 0.f);
        float h2 = fmaxf(s.z + bj.z, 0.f), h3 = fmaxf(s.w + bj.w, 0.f);
        float p3 = h0*w3.x + h1*w3.y + h2*w3.z + h3*w3.w;
        float p4 = h0*w4.x + h1*w4.y + h2*w4.z + h3*w4.w;
        float p5 = h0*w5.x + h1*w5.y + h2*w5.z + h3*w5.w;
        float p6 = h0*w6.x + h1*w6.y + h2*w6.z + h3*w6.w;

        float se = enode[(size_t)rt * 64 + lane] + enode[(size_t)rt * 64 + lane + 32];
        float sc = (lane < 4) ? ccl[rt * 4 + lane] : 0.0f;
        float sn = cnd[(size_t)rt * 32 + lane];

        #pragma unroll
        for (int off = 16; off; off >>= 1) {
            p3 += __shfl_xor_sync(0xffffffffu, p3, off);
            p4 += __shfl_xor_sync(0xffffffffu, p4, off);
            p5 += __shfl_xor_sync(0xffffffffu, p5, off);
            p6 += __shfl_xor_sync(0xffffffffu, p6, off);
            se += __shfl_xor_sync(0xffffffffu, se, off);
            sc += __shfl_xor_sync(0xffffffffu, sc, off);
            sn += __shfl_xor_sync(0xffffffffu, sn, off);
        }
        if (lane == 0 && ok) {
            float me = se * (1.0f / 64.0f);
            float ss = sc * sn;
            float y51 = 1.0f / (1.0f + expf(-(p3 * me + B3)));
            float y61 = p4 * me + B4;
            float y52 = 1.0f / (1.0f + expf(-(p5 * ss + B5)));
            float y62 = p6 * ss + B6;
            float p2 = y51 * y52;
            out[task] = (1.0f - p2) * (-100.0f) + p2 * (y61 + y62);
        }
    }
}

// -----------------------------------------------------------------------------
extern "C" void kernel_launch(void* const* d_in, const int* in_sizes, int n_in,
                              void* d_out, int out_size) {
    const float* bb    = (const float*)d_in[2];
    const float* res   = (const float*)d_in[3];
    const float* fr    = (const float*)d_in[4];
    const float* estep = (const float*)d_in[5];
    const float* enode = (const float*)d_in[6];
    const float* ccl   = (const float*)d_in[7];
    const float* cnd   = (const float*)d_in[8];
    const float* W1    = (const float*)d_in[9];
    const float* b1    = (const float*)d_in[10];
    const float* W3    = (const float*)d_in[11];
    const float* b3    = (const float*)d_in[12];
    const float* W4    = (const float*)d_in[13];
    const float* b4    = (const float*)d_in[14];
    const float* W5    = (const float*)d_in[15];
    const float* b5    = (const float*)d_in[16];
    const float* W6    = (const float*)d_in[17];
    const float* b6    = (const float*)d_in[18];

    int T = in_sizes[2] / D_BB;

    static int cfg = 0;
    if (!cfg) {
        cudaFuncSetAttribute(critic_mma,
                             cudaFuncAttributeMaxDynamicSharedMemorySize,
                             SMEM_TOTAL);
        cfg = 1;
    }

    critic_mma<<<(T + 31) / 32, 512, SMEM_TOTAL>>>(
        bb, res, fr, estep, enode, ccl, cnd, W1,
        b1, W3, b3, W4, b4, W5, b5, W6, b6, (float*)d_out, T);
}